// round 4
// baseline (speedup 1.0000x reference)
#include <cuda_runtime.h>

// Problem constants
#define BB   2
#define SS   2048
#define DD   2048
#define HH   16
#define DKH  128
#define MR   (BB*SS)        // 4096

typedef unsigned long long ull;

#define NEG_INF (__int_as_float(0xff800000))

// ---------------- f32x2 helpers (FFMA2 path, 2x fp32 throughput) ----------------
__device__ __forceinline__ void ffma2(ull &d, ull a, ull b) {
    asm("fma.rn.f32x2 %0, %1, %2, %0;" : "+l"(d) : "l"(a), "l"(b));
}
__device__ __forceinline__ void fmul2(ull &d, ull a) {
    asm("mul.rn.f32x2 %0, %0, %1;" : "+l"(d) : "l"(a));
}
__device__ __forceinline__ ull pack2(float x) {
    ull r; asm("mov.b64 %0, {%1, %1};" : "=l"(r) : "f"(x)); return r;
}
__device__ __forceinline__ float2 unpack2(ull v) {
    float2 f; asm("mov.b64 {%0, %1}, %2;" : "=f"(f.x), "=f"(f.y) : "l"(v)); return f;
}

// ---------------- scratch (static device globals; no allocation) ----------------
__device__ float g_q[BB*HH*SS*DKH];     // [b][h][s][dk]
__device__ float g_k[BB*HH*SS*DKH];
__device__ float g_v[BB*HH*SS*DKH];
__device__ float g_att[MR*DD];          // [b*s][h*dk]

// =================================================================================
// NT GEMM: C[m,n] = sum_k A[m,k] * B[n,k]
// 128x128 block tile, BK=16, 256 threads, 8x8 per thread via f32x2 pairs,
// double-buffered smem, prefetch into registers.
// mode 0: plain C write. mode 1: scatter into g_q/g_k/g_v. mode 2: A := g_att.
// All dims divide tile sizes exactly (4096 x {6144,2048} x 2048).
// =================================================================================
#define BM 128
#define BN 128
#define BKg 16

__global__ __launch_bounds__(256, 2)
void gemm_nt(const float* __restrict__ A, const float* __restrict__ Bm,
             float* __restrict__ C, int M, int N, int K, int mode)
{
    __shared__ float As[2][BKg][BM];
    __shared__ float Bs[2][BKg][BN];

    const int tid = threadIdx.x;
    const int tx  = tid & 15;
    const int ty  = tid >> 4;
    const int m0  = blockIdx.y * BM;
    const int n0  = blockIdx.x * BN;

    if (mode == 2) A = g_att;

    const int lrow = tid >> 2;          // 0..63
    const int lk   = (tid & 3) * 4;     // 0,4,8,12
    const float* Ag = A  + (size_t)(m0 + lrow) * K + lk;
    const float* Bg = Bm + (size_t)(n0 + lrow) * K + lk;

    float4 ra0, ra1, rb0, rb1;
    ra0 = *(const float4*)(Ag);
    ra1 = *(const float4*)(Ag + (size_t)64 * K);
    rb0 = *(const float4*)(Bg);
    rb1 = *(const float4*)(Bg + (size_t)64 * K);

    // store tile 0 (transposed: As[k][row])
    {
        As[0][lk+0][lrow]    = ra0.x; As[0][lk+1][lrow]    = ra0.y;
        As[0][lk+2][lrow]    = ra0.z; As[0][lk+3][lrow]    = ra0.w;
        As[0][lk+0][lrow+64] = ra1.x; As[0][lk+1][lrow+64] = ra1.y;
        As[0][lk+2][lrow+64] = ra1.z; As[0][lk+3][lrow+64] = ra1.w;
        Bs[0][lk+0][lrow]    = rb0.x; Bs[0][lk+1][lrow]    = rb0.y;
        Bs[0][lk+2][lrow]    = rb0.z; Bs[0][lk+3][lrow]    = rb0.w;
        Bs[0][lk+0][lrow+64] = rb1.x; Bs[0][lk+1][lrow+64] = rb1.y;
        Bs[0][lk+2][lrow+64] = rb1.z; Bs[0][lk+3][lrow+64] = rb1.w;
    }
    __syncthreads();

    ull acc[8][4];
    #pragma unroll
    for (int i = 0; i < 8; ++i)
        #pragma unroll
        for (int j = 0; j < 4; ++j) acc[i][j] = 0ULL;

    const int NT = K / BKg;
    int buf = 0;
    for (int t = 0; t < NT; ++t) {
        const bool pf = (t + 1 < NT);
        if (pf) {
            Ag += BKg; Bg += BKg;       // incremented pointers: no per-iter IMAD chain
            ra0 = *(const float4*)(Ag);
            ra1 = *(const float4*)(Ag + (size_t)64 * K);
            rb0 = *(const float4*)(Bg);
            rb1 = *(const float4*)(Bg + (size_t)64 * K);
        }
        #pragma unroll
        for (int k = 0; k < BKg; ++k) {
            float4 a0 = *(const float4*)&As[buf][k][ty * 4];
            float4 a1 = *(const float4*)&As[buf][k][64 + ty * 4];
            ulonglong2 bv0 = *(const ulonglong2*)&Bs[buf][k][tx * 4];
            ulonglong2 bv1 = *(const ulonglong2*)&Bs[buf][k][64 + tx * 4];
            float av[8] = {a0.x, a0.y, a0.z, a0.w, a1.x, a1.y, a1.z, a1.w};
            #pragma unroll
            for (int i = 0; i < 8; ++i) {
                ull ap = pack2(av[i]);
                ffma2(acc[i][0], ap, bv0.x);
                ffma2(acc[i][1], ap, bv0.y);
                ffma2(acc[i][2], ap, bv1.x);
                ffma2(acc[i][3], ap, bv1.y);
            }
        }
        if (pf) {
            const int nb = buf ^ 1;
            As[nb][lk+0][lrow]    = ra0.x; As[nb][lk+1][lrow]    = ra0.y;
            As[nb][lk+2][lrow]    = ra0.z; As[nb][lk+3][lrow]    = ra0.w;
            As[nb][lk+0][lrow+64] = ra1.x; As[nb][lk+1][lrow+64] = ra1.y;
            As[nb][lk+2][lrow+64] = ra1.z; As[nb][lk+3][lrow+64] = ra1.w;
            Bs[nb][lk+0][lrow]    = rb0.x; Bs[nb][lk+1][lrow]    = rb0.y;
            Bs[nb][lk+2][lrow]    = rb0.z; Bs[nb][lk+3][lrow]    = rb0.w;
            Bs[nb][lk+0][lrow+64] = rb1.x; Bs[nb][lk+1][lrow+64] = rb1.y;
            Bs[nb][lk+2][lrow+64] = rb1.z; Bs[nb][lk+3][lrow+64] = rb1.w;
        }
        __syncthreads();
        buf ^= 1;
    }

    if (mode != 1) {
        // plain row-major C
        #pragma unroll
        for (int i = 0; i < 8; ++i) {
            const int r = m0 + ((i < 4) ? (ty * 4 + i) : (64 + ty * 4 + i - 4));
            float2 c0 = unpack2(acc[i][0]);
            float2 c1 = unpack2(acc[i][1]);
            float2 c2 = unpack2(acc[i][2]);
            float2 c3 = unpack2(acc[i][3]);
            *(float4*)&C[(size_t)r * N + n0 + tx * 4]      = make_float4(c0.x, c0.y, c1.x, c1.y);
            *(float4*)&C[(size_t)r * N + n0 + 64 + tx * 4] = make_float4(c2.x, c2.y, c3.x, c3.y);
        }
    } else {
        // scatter QKV into [b][h][s][dk]; per-tile constants (BN=128 == DKH)
        const int part  = n0 >> 11;          // 0=q, 1=k, 2=v
        const int hcol  = (n0 & 2047) >> 7;  // head
        float* dst = (part == 0) ? g_q : (part == 1) ? g_k : g_v;
        const int bb    = m0 >> 11;
        const int sbase = m0 & 2047;
        float* dp = dst + (size_t)(bb * HH + hcol) * SS * DKH;
        #pragma unroll
        for (int i = 0; i < 8; ++i) {
            const int rl = (i < 4) ? (ty * 4 + i) : (64 + ty * 4 + i - 4);
            const int s  = sbase + rl;
            float2 c0 = unpack2(acc[i][0]);
            float2 c1 = unpack2(acc[i][1]);
            float2 c2 = unpack2(acc[i][2]);
            float2 c3 = unpack2(acc[i][3]);
            *(float4*)&dp[(size_t)s * DKH + tx * 4]      = make_float4(c0.x, c0.y, c1.x, c1.y);
            *(float4*)&dp[(size_t)s * DKH + 64 + tx * 4] = make_float4(c2.x, c2.y, c3.x, c3.y);
        }
    }
}

// =================================================================================
// Fused causal flash attention: one CTA = 64 queries of one (b,h).
// BM=64 queries x BN=64 keys per tile, DK=128, fp32 online softmax, FFMA2 math.
// grid = (B*H, S/64), 256 threads. Dynamic smem = 118784 B.
// bh innermost (x) so each placement wave has near-uniform qt cost; largest qt first.
// =================================================================================
#define QSTR 132
#define PSTR 68
#define ATT_SMEM_BYTES ((3*64*QSTR + 64*PSTR) * 4)

__global__ __launch_bounds__(256, 1)
void attn_fused()
{
    extern __shared__ float sm[];
    float* sQ = sm;                 // [64][132]
    float* sK = sQ + 64 * QSTR;     // [64][132]
    float* sV = sK + 64 * QSTR;     // [64][132]
    float* sP = sV + 64 * QSTR;     // [64][68]

    const int tid = threadIdx.x;
    const int tx  = tid & 15;
    const int ty  = tid >> 4;
    const int bh  = blockIdx.x;
    const int qt  = gridDim.y - 1 - blockIdx.y;   // largest-first (LPT) scheduling
    const int q0  = qt * 64;

    const float scale = 0.08838834764831845f;   // 1/sqrt(128)

    // load Q tile (pre-scaled)
    const float* Qg = g_q + ((size_t)bh * SS + q0) * DKH;
    #pragma unroll
    for (int it = 0; it < 8; ++it) {
        int f   = tid + it * 256;       // float4 index, 0..2047
        int row = f >> 5;
        int c4  = (f & 31) * 4;
        float4 v = *(const float4*)(Qg + row * DKH + c4);
        v.x *= scale; v.y *= scale; v.z *= scale; v.w *= scale;
        *(float4*)&sQ[row * QSTR + c4] = v;
    }

    float mrow[4], lsum[4];
    ull O2[4][4];
    #pragma unroll
    for (int i = 0; i < 4; ++i) {
        mrow[i] = NEG_INF; lsum[i] = 0.0f;
        #pragma unroll
        for (int j = 0; j < 4; ++j) O2[i][j] = 0ULL;
    }

    for (int t = 0; t <= qt; ++t) {
        __syncthreads();   // protect sK/sV/sP from previous iteration readers (and sQ store)
        const float* Kg = g_k + ((size_t)bh * SS + t * 64) * DKH;
        const float* Vg = g_v + ((size_t)bh * SS + t * 64) * DKH;
        #pragma unroll
        for (int it = 0; it < 8; ++it) {
            int f   = tid + it * 256;
            int row = f >> 5;
            int c4  = (f & 31) * 4;
            *(float4*)&sK[row * QSTR + c4] = *(const float4*)(Kg + row * DKH + c4);
            *(float4*)&sV[row * QSTR + c4] = *(const float4*)(Vg + row * DKH + c4);
        }
        __syncthreads();

        // scores: rows ty*4+i, cols tx+16*j, f32x2 over k pairs
        ull s2[4][4];
        #pragma unroll
        for (int i = 0; i < 4; ++i)
            #pragma unroll
            for (int j = 0; j < 4; ++j) s2[i][j] = 0ULL;

        #pragma unroll 8
        for (int k2 = 0; k2 < 64; ++k2) {
            ull qv[4], kv[4];
            #pragma unroll
            for (int i = 0; i < 4; ++i)
                qv[i] = *(const ull*)&sQ[(ty * 4 + i) * QSTR + k2 * 2];
            #pragma unroll
            for (int j = 0; j < 4; ++j)
                kv[j] = *(const ull*)&sK[(tx + 16 * j) * QSTR + k2 * 2];
            #pragma unroll
            for (int i = 0; i < 4; ++i)
                #pragma unroll
                for (int j = 0; j < 4; ++j)
                    ffma2(s2[i][j], qv[i], kv[j]);
        }

        float s[4][4];
        #pragma unroll
        for (int i = 0; i < 4; ++i)
            #pragma unroll
            for (int j = 0; j < 4; ++j) {
                float2 f2 = unpack2(s2[i][j]);
                s[i][j] = f2.x + f2.y;
            }

        if (t == qt) {  // causal mask on the diagonal tile (same tile origin)
            #pragma unroll
            for (int i = 0; i < 4; ++i)
                #pragma unroll
                for (int j = 0; j < 4; ++j)
                    if (tx + 16 * j > ty * 4 + i) s[i][j] = NEG_INF;
        }

        // online softmax per row
        #pragma unroll
        for (int i = 0; i < 4; ++i) {
            float tm = fmaxf(fmaxf(s[i][0], s[i][1]), fmaxf(s[i][2], s[i][3]));
            #pragma unroll
            for (int off = 8; off > 0; off >>= 1)
                tm = fmaxf(tm, __shfl_xor_sync(0xffffffffu, tm, off));
            float mn = fmaxf(mrow[i], tm);
            float al = __expf(mrow[i] - mn);   // 0 when mrow was -inf
            mrow[i] = mn;
            float p[4], ps = 0.0f;
            #pragma unroll
            for (int j = 0; j < 4; ++j) { p[j] = __expf(s[i][j] - mn); ps += p[j]; }
            #pragma unroll
            for (int off = 8; off > 0; off >>= 1)
                ps += __shfl_xor_sync(0xffffffffu, ps, off);
            lsum[i] = lsum[i] * al + ps;
            ull al2 = pack2(al);
            #pragma unroll
            for (int j = 0; j < 4; ++j) fmul2(O2[i][j], al2);
            #pragma unroll
            for (int j = 0; j < 4; ++j)
                sP[(ty * 4 + i) * PSTR + tx + 16 * j] = p[j];
        }
        __syncthreads();

        // O += P @ V  (cols tx*4..+3 and 64+tx*4..+3)
        #pragma unroll 4
        for (int n = 0; n < 64; ++n) {
            ulonglong2 va = *(const ulonglong2*)&sV[n * QSTR + tx * 4];
            ulonglong2 vb = *(const ulonglong2*)&sV[n * QSTR + 64 + tx * 4];
            #pragma unroll
            for (int i = 0; i < 4; ++i) {
                ull pp = pack2(sP[(ty * 4 + i) * PSTR + n]);
                ffma2(O2[i][0], pp, va.x);
                ffma2(O2[i][1], pp, va.y);
                ffma2(O2[i][2], pp, vb.x);
                ffma2(O2[i][3], pp, vb.y);
            }
        }
    }

    // epilogue: normalize and write [b][s][h*128+dk]
    const int bb = bh >> 4;
    const int hh = bh & 15;
    float* Og = g_att + ((size_t)bb * SS + q0) * DD + hh * DKH;
    #pragma unroll
    for (int i = 0; i < 4; ++i) {
        float inv = 1.0f / lsum[i];
        float2 c0 = unpack2(O2[i][0]);
        float2 c1 = unpack2(O2[i][1]);
        float2 c2 = unpack2(O2[i][2]);
        float2 c3 = unpack2(O2[i][3]);
        const int r = ty * 4 + i;
        *(float4*)&Og[(size_t)r * DD + tx * 4] =
            make_float4(c0.x * inv, c0.y * inv, c1.x * inv, c1.y * inv);
        *(float4*)&Og[(size_t)r * DD + 64 + tx * 4] =
            make_float4(c2.x * inv, c2.y * inv, c3.x * inv, c3.y * inv);
    }
}

// =================================================================================
extern "C" void kernel_launch(void* const* d_in, const int* in_sizes, int n_in,
                              void* d_out, int out_size)
{
    const float* x    = (const float*)d_in[0];
    const float* Wqkv = (const float*)d_in[1];
    const float* Wo   = (const float*)d_in[2];
    float* out = (float*)d_out;

    cudaFuncSetAttribute(attn_fused, cudaFuncAttributeMaxDynamicSharedMemorySize,
                         ATT_SMEM_BYTES);

    // 1) fused QKV projection, scattered into [b][h][s][dk]
    gemm_nt<<<dim3(3 * DD / BN, MR / BM), 256>>>(x, Wqkv, nullptr, MR, 3 * DD, DD, 1);
    // 2) fused causal attention -> g_att [b][s][d]
    attn_fused<<<dim3(BB * HH, SS / 64), 256, ATT_SMEM_BYTES>>>();
    // 3) output projection
    gemm_nt<<<dim3(DD / BN, MR / BM), 256>>>(nullptr, Wo, out, MR, DD, DD, 2);
}

// round 16
// speedup vs baseline: 1.4908x; 1.4908x over previous
#include <cuda_runtime.h>
#include <cuda_bf16.h>
#include <cstdint>

// Problem constants
#define BB   2
#define SS   2048
#define DD   2048
#define HH   16
#define DKH  128
#define MR   (BB*SS)        // 4096

typedef unsigned long long ull;
typedef unsigned short u16;
typedef unsigned int u32;

#define NEG_INF (__int_as_float(0xff800000))

// ---------------- f32x2 helpers (attention kernel) ----------------
__device__ __forceinline__ void ffma2(ull &d, ull a, ull b) {
    asm("fma.rn.f32x2 %0, %1, %2, %0;" : "+l"(d) : "l"(a), "l"(b));
}
__device__ __forceinline__ void fmul2(ull &d, ull a) {
    asm("mul.rn.f32x2 %0, %0, %1;" : "+l"(d) : "l"(a));
}
__device__ __forceinline__ ull pack2(float x) {
    ull r; asm("mov.b64 %0, {%1, %1};" : "=l"(r) : "f"(x)); return r;
}
__device__ __forceinline__ float2 unpack2(ull v) {
    float2 f; asm("mov.b64 {%0, %1}, %2;" : "=f"(f.x), "=f"(f.y) : "l"(v)); return f;
}

// ---------------- mma.sync + shared-load helpers (base ISA) ----------------
__device__ __forceinline__ u32 smem_u32(const void* p) {
    u32 a; asm("{ .reg .u64 t; cvta.to.shared.u64 t, %1; cvt.u32.u64 %0, t; }" : "=r"(a) : "l"(p));
    return a;
}
__device__ __forceinline__ u32 lds32(u32 a) {
    u32 v; asm volatile("ld.shared.b32 %0, [%1];" : "=r"(v) : "r"(a)); return v;
}
__device__ __forceinline__ void mma16816(float* d, const u32* a, u32 b0, u32 b1) {
    asm volatile("mma.sync.aligned.m16n8k16.row.col.f32.bf16.bf16.f32 "
        "{%0,%1,%2,%3},{%4,%5,%6,%7},{%8,%9},{%0,%1,%2,%3};"
        : "+f"(d[0]), "+f"(d[1]), "+f"(d[2]), "+f"(d[3])
        : "r"(a[0]), "r"(a[1]), "r"(a[2]), "r"(a[3]), "r"(b0), "r"(b1));
}

// ---------------- scratch (static device globals; referenced ONLY in device code)
__device__ float g_q[BB*HH*SS*DKH];     // [b][h][s][dk] fp32
__device__ float g_k[BB*HH*SS*DKH];
__device__ float g_v[BB*HH*SS*DKH];
__device__ u16 g_xhi[MR*DD],     g_xlo[MR*DD];        // x split
__device__ u16 g_wqhi[3*DD*DD],  g_wqlo[3*DD*DD];     // Wqkv split
__device__ u16 g_wohi[DD*DD],    g_wolo[DD*DD];       // Wo split
__device__ u16 g_ahi[MR*DD],     g_alo[MR*DD];        // attention output split

// ---------------- split fp32 -> (hi, lo) bf16; dest chosen IN DEVICE CODE --------
__global__ void split_hl(const float* __restrict__ src, int n4, int which)
{
    int i = blockIdx.x * blockDim.x + threadIdx.x;
    if (i >= n4) return;
    u16 *hi, *lo;
    if (which == 0)      { hi = g_xhi;  lo = g_xlo;  }
    else if (which == 1) { hi = g_wqhi; lo = g_wqlo; }
    else                 { hi = g_wohi; lo = g_wolo; }
    float4 v = ((const float4*)src)[i];
    ushort4 H, L;
    float h;
    h = __bfloat162float(__float2bfloat16(v.x)); H.x = __bfloat16_as_ushort(__float2bfloat16(v.x)); L.x = __bfloat16_as_ushort(__float2bfloat16(v.x - h));
    h = __bfloat162float(__float2bfloat16(v.y)); H.y = __bfloat16_as_ushort(__float2bfloat16(v.y)); L.y = __bfloat16_as_ushort(__float2bfloat16(v.y - h));
    h = __bfloat162float(__float2bfloat16(v.z)); H.z = __bfloat16_as_ushort(__float2bfloat16(v.z)); L.z = __bfloat16_as_ushort(__float2bfloat16(v.z - h));
    h = __bfloat162float(__float2bfloat16(v.w)); H.w = __bfloat16_as_ushort(__float2bfloat16(v.w)); L.w = __bfloat16_as_ushort(__float2bfloat16(v.w - h));
    ((ushort4*)hi)[i] = H;
    ((ushort4*)lo)[i] = L;
}

// =================================================================================
// bf16x3 NT GEMM via mma.sync m16n8k16: C = Ahi*Bhi + Ahi*Blo + Alo*Bhi (fp32 acc)
// A/B bound to device globals INSIDE the kernel by mode:
//   mode 1: A = x split, B = Wqkv split; scatter QKV into g_q/g_k/g_v.
//   mode 0: A = attention-output split, B = Wo split; write row-major C (harness ptr).
// 128x128 CTA tile, BK=32, 8 warps (2m x 4n). Plain LDG->STS loader, direct LDS
// fragment loads. smem: Ah | Al | Bh | Bl, each [128][40] bf16 (pad-8).
// =================================================================================
#define ARR_B  10240          // bytes per [128][40] bf16 array
#define GEMM_SMEM (4*ARR_B)   // 40960

__global__ __launch_bounds__(256)
void gemm_mma(float* __restrict__ C, int N, int K, int mode)
{
    const u16 *Ahi, *Alo, *Bhi, *Blo;
    if (mode == 1) { Ahi = g_xhi; Alo = g_xlo; Bhi = g_wqhi; Blo = g_wqlo; }
    else           { Ahi = g_ahi; Alo = g_alo; Bhi = g_wohi; Blo = g_wolo; }

    extern __shared__ char smem[];
    const u32 sb = smem_u32(smem);
    const int tid  = threadIdx.x;
    const int wid  = tid >> 5;
    const int lane = tid & 31;
    const int warp_m = wid & 1;        // 2 warps in m (64 rows each)
    const int warp_n = wid >> 1;       // 4 warps in n (32 cols each)
    const int m0 = blockIdx.y * 128;
    const int n0 = blockIdx.x * 128;

    // fragment lane addressing (PTX m16n8k16 layout)
    const int grp = lane >> 2;          // 0..7
    const int tig = lane & 3;           // 0..3
    const u32 kb = (u32)tig * 4;

    float acc[4][4][4];
    #pragma unroll
    for (int i = 0; i < 4; ++i)
        #pragma unroll
        for (int j = 0; j < 4; ++j)
            #pragma unroll
            for (int q = 0; q < 4; ++q) acc[i][j][q] = 0.0f;

    const int NT = K / 32;
    for (int t = 0; t < NT; ++t) {
        __syncthreads();   // previous chunk's readers done
        // ---- load chunk t: 128 rows x 32 bf16 (64B) per array ----
        #pragma unroll
        for (int hf = 0; hf < 2; ++hf) {
            int u   = tid + hf * 256;      // 0..511
            int row = u >> 2;              // 0..127
            int seg = u & 3;               // 4 x 16B
            size_t ao = (size_t)(m0 + row) * K + t * 32 + seg * 8;
            size_t bo = (size_t)(n0 + row) * K + t * 32 + seg * 8;
            char* d = smem + row * 80 + seg * 16;
            *(uint4*)(d + 0 * ARR_B) = *(const uint4*)(Ahi + ao);
            *(uint4*)(d + 1 * ARR_B) = *(const uint4*)(Alo + ao);
            *(uint4*)(d + 2 * ARR_B) = *(const uint4*)(Bhi + bo);
            *(uint4*)(d + 3 * ARR_B) = *(const uint4*)(Blo + bo);
        }
        __syncthreads();

        // ---- compute: 2 k16 steps ----
        #pragma unroll
        for (int ks = 0; ks < 2; ++ks) {
            const u32 kso = ks * 32;    // 16 bf16 = 32 bytes

            u32 bh[4][2], bl[4][2];
            #pragma unroll
            for (int nf = 0; nf < 4; ++nf) {
                const u32 baddr = sb + (u32)((warp_n * 32 + nf * 8 + grp) * 80) + kb + kso;
                bh[nf][0] = lds32(baddr + 2 * ARR_B);
                bh[nf][1] = lds32(baddr + 2 * ARR_B + 16);
                bl[nf][0] = lds32(baddr + 3 * ARR_B);
                bl[nf][1] = lds32(baddr + 3 * ARR_B + 16);
            }

            // Ahi fragments: hi*hi and hi*lo terms
            #pragma unroll
            for (int mf = 0; mf < 4; ++mf) {
                const u32 aaddr = sb + (u32)((warp_m * 64 + mf * 16 + grp) * 80) + kb + kso;
                u32 ah[4];
                ah[0] = lds32(aaddr);                 // row grp,   k 0-7
                ah[1] = lds32(aaddr + 8 * 80);        // row grp+8, k 0-7
                ah[2] = lds32(aaddr + 16);            // row grp,   k 8-15
                ah[3] = lds32(aaddr + 8 * 80 + 16);   // row grp+8, k 8-15
                #pragma unroll
                for (int nf = 0; nf < 4; ++nf) {
                    mma16816(acc[mf][nf], ah, bh[nf][0], bh[nf][1]);
                    mma16816(acc[mf][nf], ah, bl[nf][0], bl[nf][1]);
                }
            }
            // Alo fragments: lo*hi term
            #pragma unroll
            for (int mf = 0; mf < 4; ++mf) {
                const u32 aaddr = sb + ARR_B + (u32)((warp_m * 64 + mf * 16 + grp) * 80) + kb + kso;
                u32 al[4];
                al[0] = lds32(aaddr);
                al[1] = lds32(aaddr + 8 * 80);
                al[2] = lds32(aaddr + 16);
                al[3] = lds32(aaddr + 8 * 80 + 16);
                #pragma unroll
                for (int nf = 0; nf < 4; ++nf)
                    mma16816(acc[mf][nf], al, bh[nf][0], bh[nf][1]);
            }
        }
    }

    // ---------------- epilogue ----------------
    const int rbase = warp_m * 64 + grp;
    const int cbase = warp_n * 32 + tig * 2;
    if (mode == 0) {
        #pragma unroll
        for (int mf = 0; mf < 4; ++mf) {
            const int r0 = m0 + rbase + mf * 16;
            #pragma unroll
            for (int nf = 0; nf < 4; ++nf) {
                const int c = n0 + cbase + nf * 8;
                *(float2*)&C[(size_t)r0 * N + c]       = make_float2(acc[mf][nf][0], acc[mf][nf][1]);
                *(float2*)&C[(size_t)(r0 + 8) * N + c] = make_float2(acc[mf][nf][2], acc[mf][nf][3]);
            }
        }
    } else {
        // whole 128-wide n-tile belongs to one (part, head)
        const int part = n0 >> 11;
        const int hcol = (n0 & 2047) >> 7;
        float* dst = (part == 0) ? g_q : (part == 1) ? g_k : g_v;
        const int bb = m0 >> 11;
        const int sbase2 = m0 & 2047;
        float* dp = dst + (size_t)(bb * HH + hcol) * SS * DKH;
        #pragma unroll
        for (int mf = 0; mf < 4; ++mf) {
            const int s0 = sbase2 + rbase + mf * 16;
            #pragma unroll
            for (int nf = 0; nf < 4; ++nf) {
                const int dk = cbase + nf * 8;
                *(float2*)&dp[(size_t)s0 * DKH + dk]       = make_float2(acc[mf][nf][0], acc[mf][nf][1]);
                *(float2*)&dp[(size_t)(s0 + 8) * DKH + dk] = make_float2(acc[mf][nf][2], acc[mf][nf][3]);
            }
        }
    }
}

// =================================================================================
// Fused causal flash attention (FFMA2, R4-proven math); epilogue writes hi/lo bf16
// to g_ahi/g_alo (device-code references). grid = (B*H, S/64), 256 threads, LPT.
// =================================================================================
#define QSTR 132
#define PSTR 68
#define ATT_SMEM_BYTES ((3*64*QSTR + 64*PSTR) * 4)

__device__ __forceinline__ u32 bf2pack(float a, float b) {
    __nv_bfloat162 t = __floats2bfloat162_rn(a, b);   // x=a (low addr), y=b
    return *reinterpret_cast<u32*>(&t);
}

__global__ __launch_bounds__(256, 1)
void attn_fused()
{
    extern __shared__ float sm[];
    float* sQ = sm;                 // [64][132]
    float* sK = sQ + 64 * QSTR;
    float* sV = sK + 64 * QSTR;
    float* sP = sV + 64 * QSTR;     // [64][68]

    const int tid = threadIdx.x;
    const int tx  = tid & 15;
    const int ty  = tid >> 4;
    const int bh  = blockIdx.x;
    const int qt  = gridDim.y - 1 - blockIdx.y;
    const int q0  = qt * 64;

    const float scale = 0.08838834764831845f;

    const float* Qg = g_q + ((size_t)bh * SS + q0) * DKH;
    #pragma unroll
    for (int it = 0; it < 8; ++it) {
        int f = tid + it * 256;
        int row = f >> 5;
        int c4 = (f & 31) * 4;
        float4 v = *(const float4*)(Qg + row * DKH + c4);
        v.x *= scale; v.y *= scale; v.z *= scale; v.w *= scale;
        *(float4*)&sQ[row * QSTR + c4] = v;
    }

    float mrow[4], lsum[4];
    ull O2[4][4];
    #pragma unroll
    for (int i = 0; i < 4; ++i) {
        mrow[i] = NEG_INF; lsum[i] = 0.0f;
        #pragma unroll
        for (int j = 0; j < 4; ++j) O2[i][j] = 0ULL;
    }

    for (int t = 0; t <= qt; ++t) {
        __syncthreads();
        const float* Kg = g_k + ((size_t)bh * SS + t * 64) * DKH;
        const float* Vg = g_v + ((size_t)bh * SS + t * 64) * DKH;
        #pragma unroll
        for (int it = 0; it < 8; ++it) {
            int f = tid + it * 256;
            int row = f >> 5;
            int c4 = (f & 31) * 4;
            *(float4*)&sK[row * QSTR + c4] = *(const float4*)(Kg + row * DKH + c4);
            *(float4*)&sV[row * QSTR + c4] = *(const float4*)(Vg + row * DKH + c4);
        }
        __syncthreads();

        ull s2[4][4];
        #pragma unroll
        for (int i = 0; i < 4; ++i)
            #pragma unroll
            for (int j = 0; j < 4; ++j) s2[i][j] = 0ULL;

        #pragma unroll 8
        for (int k2 = 0; k2 < 64; ++k2) {
            ull qv[4], kv[4];
            #pragma unroll
            for (int i = 0; i < 4; ++i)
                qv[i] = *(const ull*)&sQ[(ty * 4 + i) * QSTR + k2 * 2];
            #pragma unroll
            for (int j = 0; j < 4; ++j)
                kv[j] = *(const ull*)&sK[(tx + 16 * j) * QSTR + k2 * 2];
            #pragma unroll
            for (int i = 0; i < 4; ++i)
                #pragma unroll
                for (int j = 0; j < 4; ++j)
                    ffma2(s2[i][j], qv[i], kv[j]);
        }

        float s[4][4];
        #pragma unroll
        for (int i = 0; i < 4; ++i)
            #pragma unroll
            for (int j = 0; j < 4; ++j) {
                float2 f2 = unpack2(s2[i][j]);
                s[i][j] = f2.x + f2.y;
            }

        if (t == qt) {
            #pragma unroll
            for (int i = 0; i < 4; ++i)
                #pragma unroll
                for (int j = 0; j < 4; ++j)
                    if (tx + 16 * j > ty * 4 + i) s[i][j] = NEG_INF;
        }

        #pragma unroll
        for (int i = 0; i < 4; ++i) {
            float tm = fmaxf(fmaxf(s[i][0], s[i][1]), fmaxf(s[i][2], s[i][3]));
            #pragma unroll
            for (int off = 8; off > 0; off >>= 1)
                tm = fmaxf(tm, __shfl_xor_sync(0xffffffffu, tm, off));
            float mn = fmaxf(mrow[i], tm);
            float al = __expf(mrow[i] - mn);
            mrow[i] = mn;
            float p[4], ps = 0.0f;
            #pragma unroll
            for (int j = 0; j < 4; ++j) { p[j] = __expf(s[i][j] - mn); ps += p[j]; }
            #pragma unroll
            for (int off = 8; off > 0; off >>= 1)
                ps += __shfl_xor_sync(0xffffffffu, ps, off);
            lsum[i] = lsum[i] * al + ps;
            ull al2 = pack2(al);
            #pragma unroll
            for (int j = 0; j < 4; ++j) fmul2(O2[i][j], al2);
            #pragma unroll
            for (int j = 0; j < 4; ++j)
                sP[(ty * 4 + i) * PSTR + tx + 16 * j] = p[j];
        }
        __syncthreads();

        #pragma unroll 4
        for (int n = 0; n < 64; ++n) {
            ulonglong2 va = *(const ulonglong2*)&sV[n * QSTR + tx * 4];
            ulonglong2 vb = *(const ulonglong2*)&sV[n * QSTR + 64 + tx * 4];
            #pragma unroll
            for (int i = 0; i < 4; ++i) {
                ull pp = pack2(sP[(ty * 4 + i) * PSTR + n]);
                ffma2(O2[i][0], pp, va.x);
                ffma2(O2[i][1], pp, va.y);
                ffma2(O2[i][2], pp, vb.x);
                ffma2(O2[i][3], pp, vb.y);
            }
        }
    }

    // epilogue: normalize + split to hi/lo bf16 in [b*s][h*dk] layout
    const int bb = bh >> 4;
    const int hh = bh & 15;
    u16* Hg = g_ahi + ((size_t)bb * SS + q0) * DD + hh * DKH;
    u16* Lg = g_alo + ((size_t)bb * SS + q0) * DD + hh * DKH;
    #pragma unroll
    for (int i = 0; i < 4; ++i) {
        float inv = 1.0f / lsum[i];
        float2 c0 = unpack2(O2[i][0]);
        float2 c1 = unpack2(O2[i][1]);
        float2 c2 = unpack2(O2[i][2]);
        float2 c3 = unpack2(O2[i][3]);
        float o[8] = {c0.x*inv, c0.y*inv, c1.x*inv, c1.y*inv,
                      c2.x*inv, c2.y*inv, c3.x*inv, c3.y*inv};
        float hv[8], lv[8];
        #pragma unroll
        for (int q = 0; q < 8; ++q) {
            hv[q] = __bfloat162float(__float2bfloat16(o[q]));
            lv[q] = o[q] - hv[q];
        }
        const int r = ty * 4 + i;
        *(uint2*)&Hg[(size_t)r * DD + tx * 4]      = make_uint2(bf2pack(hv[0], hv[1]), bf2pack(hv[2], hv[3]));
        *(uint2*)&Hg[(size_t)r * DD + 64 + tx * 4] = make_uint2(bf2pack(hv[4], hv[5]), bf2pack(hv[6], hv[7]));
        *(uint2*)&Lg[(size_t)r * DD + tx * 4]      = make_uint2(bf2pack(lv[0], lv[1]), bf2pack(lv[2], lv[3]));
        *(uint2*)&Lg[(size_t)r * DD + 64 + tx * 4] = make_uint2(bf2pack(lv[4], lv[5]), bf2pack(lv[6], lv[7]));
    }
}

// =================================================================================
extern "C" void kernel_launch(void* const* d_in, const int* in_sizes, int n_in,
                              void* d_out, int out_size)
{
    const float* x    = (const float*)d_in[0];
    const float* Wqkv = (const float*)d_in[1];
    const float* Wo   = (const float*)d_in[2];
    float* out = (float*)d_out;

    cudaFuncSetAttribute(attn_fused, cudaFuncAttributeMaxDynamicSharedMemorySize,
                         ATT_SMEM_BYTES);
    cudaFuncSetAttribute(gemm_mma, cudaFuncAttributeMaxDynamicSharedMemorySize,
                         GEMM_SMEM);

    // 0) split inputs into hi/lo bf16 (dest globals selected in device code)
    split_hl<<<((MR * DD / 4)     + 255) / 256, 256>>>(x,    MR * DD / 4,     0);
    split_hl<<<((3 * DD * DD / 4) + 255) / 256, 256>>>(Wqkv, 3 * DD * DD / 4, 1);
    split_hl<<<((DD * DD / 4)     + 255) / 256, 256>>>(Wo,   DD * DD / 4,     2);
    // 1) QKV projection (mma.sync bf16x3), scatter into g_q/g_k/g_v
    gemm_mma<<<dim3(3 * DD / 128, MR / 128), 256, GEMM_SMEM>>>(nullptr, 3 * DD, DD, 1);
    // 2) fused causal attention -> hi/lo bf16 g_ahi/g_alo
    attn_fused<<<dim3(BB * HH, SS / 64), 256, ATT_SMEM_BYTES>>>();
    // 3) output projection (mma.sync bf16x3) -> d_out
    gemm_mma<<<dim3(DD / 128, MR / 128), 256, GEMM_SMEM>>>(out, DD, DD, 0);
}

// round 17
// speedup vs baseline: 1.6508x; 1.1073x over previous
#include <cuda_runtime.h>
#include <cuda_bf16.h>
#include <cstdint>

// Problem constants
#define BB   2
#define SS   2048
#define DD   2048
#define HH   16
#define DKH  128
#define MR   (BB*SS)        // 4096

typedef unsigned long long ull;
typedef unsigned short u16;
typedef unsigned int u32;

#define NEG_INF (__int_as_float(0xff800000))

// ---------------- f32x2 helpers (attention kernel) ----------------
__device__ __forceinline__ void ffma2(ull &d, ull a, ull b) {
    asm("fma.rn.f32x2 %0, %1, %2, %0;" : "+l"(d) : "l"(a), "l"(b));
}
__device__ __forceinline__ void fmul2(ull &d, ull a) {
    asm("mul.rn.f32x2 %0, %0, %1;" : "+l"(d) : "l"(a));
}
__device__ __forceinline__ ull pack2(float x) {
    ull r; asm("mov.b64 %0, {%1, %1};" : "=l"(r) : "f"(x)); return r;
}
__device__ __forceinline__ float2 unpack2(ull v) {
    float2 f; asm("mov.b64 {%0, %1}, %2;" : "=f"(f.x), "=f"(f.y) : "l"(v)); return f;
}

// ---------------- mma.sync / ldmatrix / cp.async helpers (base ISA) --------------
__device__ __forceinline__ u32 smem_u32(const void* p) {
    u32 a; asm("{ .reg .u64 t; cvta.to.shared.u64 t, %1; cvt.u32.u64 %0, t; }" : "=r"(a) : "l"(p));
    return a;
}
__device__ __forceinline__ void ldsm4(u32* r, u32 addr) {
    asm volatile("ldmatrix.sync.aligned.m8n8.x4.shared.b16 {%0,%1,%2,%3}, [%4];"
        : "=r"(r[0]), "=r"(r[1]), "=r"(r[2]), "=r"(r[3]) : "r"(addr));
}
__device__ __forceinline__ void mma16816(float* d, const u32* a, u32 b0, u32 b1) {
    asm volatile("mma.sync.aligned.m16n8k16.row.col.f32.bf16.bf16.f32 "
        "{%0,%1,%2,%3},{%4,%5,%6,%7},{%8,%9},{%0,%1,%2,%3};"
        : "+f"(d[0]), "+f"(d[1]), "+f"(d[2]), "+f"(d[3])
        : "r"(a[0]), "r"(a[1]), "r"(a[2]), "r"(a[3]), "r"(b0), "r"(b1));
}
__device__ __forceinline__ void cpa16(u32 saddr, const void* g) {
    asm volatile("cp.async.cg.shared.global [%0], [%1], 16;" :: "r"(saddr), "l"(g));
}
#define CP_COMMIT() asm volatile("cp.async.commit_group;" ::: "memory")
#define CP_WAIT(n)  asm volatile("cp.async.wait_group %0;" :: "n"(n) : "memory")

// ---------------- scratch (static device globals; referenced ONLY in device code)
__device__ float g_q[BB*HH*SS*DKH];     // [b][h][s][dk] fp32
__device__ float g_k[BB*HH*SS*DKH];
__device__ float g_v[BB*HH*SS*DKH];
__device__ u16 g_xhi[MR*DD],     g_xlo[MR*DD];        // x split
__device__ u16 g_wqhi[3*DD*DD],  g_wqlo[3*DD*DD];     // Wqkv split
__device__ u16 g_wohi[DD*DD],    g_wolo[DD*DD];       // Wo split
__device__ u16 g_ahi[MR*DD],     g_alo[MR*DD];        // attention output split

// ---------------- split fp32 -> (hi, lo) bf16; dest chosen IN DEVICE CODE --------
__global__ void split_hl(const float* __restrict__ src, int n4, int which)
{
    int i = blockIdx.x * blockDim.x + threadIdx.x;
    if (i >= n4) return;
    u16 *hi, *lo;
    if (which == 0)      { hi = g_xhi;  lo = g_xlo;  }
    else if (which == 1) { hi = g_wqhi; lo = g_wqlo; }
    else                 { hi = g_wohi; lo = g_wolo; }
    float4 v = ((const float4*)src)[i];
    ushort4 H, L;
    float h;
    h = __bfloat162float(__float2bfloat16(v.x)); H.x = __bfloat16_as_ushort(__float2bfloat16(v.x)); L.x = __bfloat16_as_ushort(__float2bfloat16(v.x - h));
    h = __bfloat162float(__float2bfloat16(v.y)); H.y = __bfloat16_as_ushort(__float2bfloat16(v.y)); L.y = __bfloat16_as_ushort(__float2bfloat16(v.y - h));
    h = __bfloat162float(__float2bfloat16(v.z)); H.z = __bfloat16_as_ushort(__float2bfloat16(v.z)); L.z = __bfloat16_as_ushort(__float2bfloat16(v.z - h));
    h = __bfloat162float(__float2bfloat16(v.w)); H.w = __bfloat16_as_ushort(__float2bfloat16(v.w)); L.w = __bfloat16_as_ushort(__float2bfloat16(v.w - h));
    ((ushort4*)hi)[i] = H;
    ((ushort4*)lo)[i] = L;
}

// =================================================================================
// bf16x3 NT GEMM via mma.sync m16n8k16: C = Ahi*Bhi + Ahi*Blo + Alo*Bhi (fp32 acc)
// A/B bound to device globals INSIDE the kernel by mode (host-arg bug fix retained):
//   mode 1: A = x split, B = Wqkv split; scatter QKV into g_q/g_k/g_v.
//   mode 0: A = attn-out split, B = Wo split; write row-major C (harness ptr).
// 128x128 CTA tile, BK=32, 8 warps (2m x 4n), cp.async DOUBLE buffer + ldmatrix.
// smem/buffer: Ah | Al | Bh | Bl, each [128][40] bf16 (pad-8, conflict-free LDSM).
// =================================================================================
#define ARR_B  10240           // bytes per [128][40] bf16 array
#define BUF_B  (4*ARR_B)       // 40960
#define GEMM_SMEM (2*BUF_B)    // 81920

__device__ __forceinline__ void load_chunk(u32 sbuf,
    const u16* __restrict__ Ahi, const u16* __restrict__ Alo,
    const u16* __restrict__ Bhi, const u16* __restrict__ Blo,
    int K, int m0, int n0, int kc, int tid)
{
    #pragma unroll
    for (int hf = 0; hf < 2; ++hf) {
        int u   = tid + hf * 256;      // 0..511
        int row = u >> 2;              // 0..127
        int seg = u & 3;               // 4 x 16B per 64B of row data
        size_t ao = (size_t)(m0 + row) * K + kc + seg * 8;
        size_t bo = (size_t)(n0 + row) * K + kc + seg * 8;
        u32 d = sbuf + row * 80 + seg * 16;
        cpa16(d + 0 * ARR_B, Ahi + ao);
        cpa16(d + 1 * ARR_B, Alo + ao);
        cpa16(d + 2 * ARR_B, Bhi + bo);
        cpa16(d + 3 * ARR_B, Blo + bo);
    }
}

__global__ __launch_bounds__(256)
void gemm_mma(float* __restrict__ C, int N, int K, int mode)
{
    const u16 *Ahi, *Alo, *Bhi, *Blo;
    if (mode == 1) { Ahi = g_xhi; Alo = g_xlo; Bhi = g_wqhi; Blo = g_wqlo; }
    else           { Ahi = g_ahi; Alo = g_alo; Bhi = g_wohi; Blo = g_wolo; }

    extern __shared__ char smem[];
    const u32 sb = smem_u32(smem);
    const int tid  = threadIdx.x;
    const int wid  = tid >> 5;
    const int lane = tid & 31;
    const int warp_m = wid & 1;        // 2 warps in m (64 rows each)
    const int warp_n = wid >> 1;       // 4 warps in n (32 cols each)
    const int m0 = blockIdx.y * 128;
    const int n0 = blockIdx.x * 128;

    // ldmatrix lane addressing
    const int a_row = lane & 15;                     // A: rows 0-15, then k-halves
    const int a_co8 = (lane >> 4) * 16;              // byte offset of k 8..15 half
    const int b_n   = (lane & 7) + ((lane >> 4) & 1) * 8;   // B: n within 16-group
    const int b_co8 = ((lane >> 3) & 1) * 16;        // byte offset of k half
    const u32 aBase = (u32)((warp_m * 64 + a_row) * 80) + a_co8;
    const u32 bBase = (u32)((warp_n * 32 + b_n) * 80) + b_co8;

    float acc[4][4][4];
    #pragma unroll
    for (int i = 0; i < 4; ++i)
        #pragma unroll
        for (int j = 0; j < 4; ++j)
            #pragma unroll
            for (int q = 0; q < 4; ++q) acc[i][j][q] = 0.0f;

    load_chunk(sb, Ahi, Alo, Bhi, Blo, K, m0, n0, 0, tid);
    CP_COMMIT();

    const int NT = K / 32;
    for (int t = 0; t < NT; ++t) {
        if (t + 1 < NT) {
            load_chunk(sb + ((t + 1) & 1) * BUF_B, Ahi, Alo, Bhi, Blo,
                       K, m0, n0, (t + 1) * 32, tid);
            CP_COMMIT();
            CP_WAIT(1);
        } else {
            CP_WAIT(0);
        }
        __syncthreads();

        const u32 base = sb + (t & 1) * BUF_B;
        #pragma unroll
        for (int ks = 0; ks < 2; ++ks) {
            const u32 kso = ks * 32;    // 16 bf16 = 32 bytes

            // B fragments: nf16 = n-group of 16; regs r0,r1 = b0,b1 of low 8n,
            // r2,r3 = b0,b1 of high 8n.
            u32 bh[2][4], bl[2][4];
            #pragma unroll
            for (int nf16 = 0; nf16 < 2; ++nf16) {
                ldsm4(bh[nf16], base + 2 * ARR_B + bBase + nf16 * (16 * 80) + kso);
                ldsm4(bl[nf16], base + 3 * ARR_B + bBase + nf16 * (16 * 80) + kso);
            }
            // Ahi fragments: hi*hi + hi*lo
            #pragma unroll
            for (int mf = 0; mf < 4; ++mf) {
                u32 ah[4];
                ldsm4(ah, base + 0 * ARR_B + aBase + mf * (16 * 80) + kso);
                #pragma unroll
                for (int nf = 0; nf < 4; ++nf) {
                    mma16816(acc[mf][nf], ah, bh[nf >> 1][(nf & 1) * 2], bh[nf >> 1][(nf & 1) * 2 + 1]);
                    mma16816(acc[mf][nf], ah, bl[nf >> 1][(nf & 1) * 2], bl[nf >> 1][(nf & 1) * 2 + 1]);
                }
            }
            // Alo fragments: lo*hi
            #pragma unroll
            for (int mf = 0; mf < 4; ++mf) {
                u32 al[4];
                ldsm4(al, base + 1 * ARR_B + aBase + mf * (16 * 80) + kso);
                #pragma unroll
                for (int nf = 0; nf < 4; ++nf)
                    mma16816(acc[mf][nf], al, bh[nf >> 1][(nf & 1) * 2], bh[nf >> 1][(nf & 1) * 2 + 1]);
            }
        }
        __syncthreads();
    }

    // ---------------- epilogue ----------------
    const int grp = lane >> 2;
    const int tig = lane & 3;
    const int rbase = warp_m * 64 + grp;
    const int cbase = warp_n * 32 + tig * 2;
    if (mode == 0) {
        #pragma unroll
        for (int mf = 0; mf < 4; ++mf) {
            const int r0 = m0 + rbase + mf * 16;
            #pragma unroll
            for (int nf = 0; nf < 4; ++nf) {
                const int c = n0 + cbase + nf * 8;
                *(float2*)&C[(size_t)r0 * N + c]       = make_float2(acc[mf][nf][0], acc[mf][nf][1]);
                *(float2*)&C[(size_t)(r0 + 8) * N + c] = make_float2(acc[mf][nf][2], acc[mf][nf][3]);
            }
        }
    } else {
        const int part = n0 >> 11;
        const int hcol = (n0 & 2047) >> 7;
        float* dst = (part == 0) ? g_q : (part == 1) ? g_k : g_v;
        const int bb = m0 >> 11;
        const int sbase2 = m0 & 2047;
        float* dp = dst + (size_t)(bb * HH + hcol) * SS * DKH;
        #pragma unroll
        for (int mf = 0; mf < 4; ++mf) {
            const int s0 = sbase2 + rbase + mf * 16;
            #pragma unroll
            for (int nf = 0; nf < 4; ++nf) {
                const int dk = cbase + nf * 8;
                *(float2*)&dp[(size_t)s0 * DKH + dk]       = make_float2(acc[mf][nf][0], acc[mf][nf][1]);
                *(float2*)&dp[(size_t)(s0 + 8) * DKH + dk] = make_float2(acc[mf][nf][2], acc[mf][nf][3]);
            }
        }
    }
}

// =================================================================================
// Fused causal flash attention (FFMA2, proven); epilogue writes hi/lo bf16 to
// g_ahi/g_alo. grid = (B*H, S/64), 256 threads, LPT on qt.
// =================================================================================
#define QSTR 132
#define PSTR 68
#define ATT_SMEM_BYTES ((3*64*QSTR + 64*PSTR) * 4)

__device__ __forceinline__ u32 bf2pack(float a, float b) {
    __nv_bfloat162 t = __floats2bfloat162_rn(a, b);
    return *reinterpret_cast<u32*>(&t);
}

__global__ __launch_bounds__(256, 1)
void attn_fused()
{
    extern __shared__ float sm[];
    float* sQ = sm;
    float* sK = sQ + 64 * QSTR;
    float* sV = sK + 64 * QSTR;
    float* sP = sV + 64 * QSTR;

    const int tid = threadIdx.x;
    const int tx  = tid & 15;
    const int ty  = tid >> 4;
    const int bh  = blockIdx.x;
    const int qt  = gridDim.y - 1 - blockIdx.y;
    const int q0  = qt * 64;

    const float scale = 0.08838834764831845f;

    const float* Qg = g_q + ((size_t)bh * SS + q0) * DKH;
    #pragma unroll
    for (int it = 0; it < 8; ++it) {
        int f = tid + it * 256;
        int row = f >> 5;
        int c4 = (f & 31) * 4;
        float4 v = *(const float4*)(Qg + row * DKH + c4);
        v.x *= scale; v.y *= scale; v.z *= scale; v.w *= scale;
        *(float4*)&sQ[row * QSTR + c4] = v;
    }

    float mrow[4], lsum[4];
    ull O2[4][4];
    #pragma unroll
    for (int i = 0; i < 4; ++i) {
        mrow[i] = NEG_INF; lsum[i] = 0.0f;
        #pragma unroll
        for (int j = 0; j < 4; ++j) O2[i][j] = 0ULL;
    }

    for (int t = 0; t <= qt; ++t) {
        __syncthreads();
        const float* Kg = g_k + ((size_t)bh * SS + t * 64) * DKH;
        const float* Vg = g_v + ((size_t)bh * SS + t * 64) * DKH;
        #pragma unroll
        for (int it = 0; it < 8; ++it) {
            int f = tid + it * 256;
            int row = f >> 5;
            int c4 = (f & 31) * 4;
            *(float4*)&sK[row * QSTR + c4] = *(const float4*)(Kg + row * DKH + c4);
            *(float4*)&sV[row * QSTR + c4] = *(const float4*)(Vg + row * DKH + c4);
        }
        __syncthreads();

        ull s2[4][4];
        #pragma unroll
        for (int i = 0; i < 4; ++i)
            #pragma unroll
            for (int j = 0; j < 4; ++j) s2[i][j] = 0ULL;

        #pragma unroll 8
        for (int k2 = 0; k2 < 64; ++k2) {
            ull qv[4], kv[4];
            #pragma unroll
            for (int i = 0; i < 4; ++i)
                qv[i] = *(const ull*)&sQ[(ty * 4 + i) * QSTR + k2 * 2];
            #pragma unroll
            for (int j = 0; j < 4; ++j)
                kv[j] = *(const ull*)&sK[(tx + 16 * j) * QSTR + k2 * 2];
            #pragma unroll
            for (int i = 0; i < 4; ++i)
                #pragma unroll
                for (int j = 0; j < 4; ++j)
                    ffma2(s2[i][j], qv[i], kv[j]);
        }

        float s[4][4];
        #pragma unroll
        for (int i = 0; i < 4; ++i)
            #pragma unroll
            for (int j = 0; j < 4; ++j) {
                float2 f2 = unpack2(s2[i][j]);
                s[i][j] = f2.x + f2.y;
            }

        if (t == qt) {
            #pragma unroll
            for (int i = 0; i < 4; ++i)
                #pragma unroll
                for (int j = 0; j < 4; ++j)
                    if (tx + 16 * j > ty * 4 + i) s[i][j] = NEG_INF;
        }

        #pragma unroll
        for (int i = 0; i < 4; ++i) {
            float tm = fmaxf(fmaxf(s[i][0], s[i][1]), fmaxf(s[i][2], s[i][3]));
            #pragma unroll
            for (int off = 8; off > 0; off >>= 1)
                tm = fmaxf(tm, __shfl_xor_sync(0xffffffffu, tm, off));
            float mn = fmaxf(mrow[i], tm);
            float al = __expf(mrow[i] - mn);
            mrow[i] = mn;
            float p[4], ps = 0.0f;
            #pragma unroll
            for (int j = 0; j < 4; ++j) { p[j] = __expf(s[i][j] - mn); ps += p[j]; }
            #pragma unroll
            for (int off = 8; off > 0; off >>= 1)
                ps += __shfl_xor_sync(0xffffffffu, ps, off);
            lsum[i] = lsum[i] * al + ps;
            ull al2 = pack2(al);
            #pragma unroll
            for (int j = 0; j < 4; ++j) fmul2(O2[i][j], al2);
            #pragma unroll
            for (int j = 0; j < 4; ++j)
                sP[(ty * 4 + i) * PSTR + tx + 16 * j] = p[j];
        }
        __syncthreads();

        #pragma unroll 4
        for (int n = 0; n < 64; ++n) {
            ulonglong2 va = *(const ulonglong2*)&sV[n * QSTR + tx * 4];
            ulonglong2 vb = *(const ulonglong2*)&sV[n * QSTR + 64 + tx * 4];
            #pragma unroll
            for (int i = 0; i < 4; ++i) {
                ull pp = pack2(sP[(ty * 4 + i) * PSTR + n]);
                ffma2(O2[i][0], pp, va.x);
                ffma2(O2[i][1], pp, va.y);
                ffma2(O2[i][2], pp, vb.x);
                ffma2(O2[i][3], pp, vb.y);
            }
        }
    }

    // epilogue: normalize + split to hi/lo bf16 in [b*s][h*dk] layout
    const int bb = bh >> 4;
    const int hh = bh & 15;
    u16* Hg = g_ahi + ((size_t)bb * SS + q0) * DD + hh * DKH;
    u16* Lg = g_alo + ((size_t)bb * SS + q0) * DD + hh * DKH;
    #pragma unroll
    for (int i = 0; i < 4; ++i) {
        float inv = 1.0f / lsum[i];
        float2 c0 = unpack2(O2[i][0]);
        float2 c1 = unpack2(O2[i][1]);
        float2 c2 = unpack2(O2[i][2]);
        float2 c3 = unpack2(O2[i][3]);
        float o[8] = {c0.x*inv, c0.y*inv, c1.x*inv, c1.y*inv,
                      c2.x*inv, c2.y*inv, c3.x*inv, c3.y*inv};
        float hv[8], lv[8];
        #pragma unroll
        for (int q = 0; q < 8; ++q) {
            hv[q] = __bfloat162float(__float2bfloat16(o[q]));
            lv[q] = o[q] - hv[q];
        }
        const int r = ty * 4 + i;
        *(uint2*)&Hg[(size_t)r * DD + tx * 4]      = make_uint2(bf2pack(hv[0], hv[1]), bf2pack(hv[2], hv[3]));
        *(uint2*)&Hg[(size_t)r * DD + 64 + tx * 4] = make_uint2(bf2pack(hv[4], hv[5]), bf2pack(hv[6], hv[7]));
        *(uint2*)&Lg[(size_t)r * DD + tx * 4]      = make_uint2(bf2pack(lv[0], lv[1]), bf2pack(lv[2], lv[3]));
        *(uint2*)&Lg[(size_t)r * DD + 64 + tx * 4] = make_uint2(bf2pack(lv[4], lv[5]), bf2pack(lv[6], lv[7]));
    }
}

// =================================================================================
extern "C" void kernel_launch(void* const* d_in, const int* in_sizes, int n_in,
                              void* d_out, int out_size)
{
    const float* x    = (const float*)d_in[0];
    const float* Wqkv = (const float*)d_in[1];
    const float* Wo   = (const float*)d_in[2];
    float* out = (float*)d_out;

    cudaFuncSetAttribute(attn_fused, cudaFuncAttributeMaxDynamicSharedMemorySize,
                         ATT_SMEM_BYTES);
    cudaFuncSetAttribute(gemm_mma, cudaFuncAttributeMaxDynamicSharedMemorySize,
                         GEMM_SMEM);

    // 0) split inputs into hi/lo bf16 (dest globals selected in device code)
    split_hl<<<((MR * DD / 4)     + 255) / 256, 256>>>(x,    MR * DD / 4,     0);
    split_hl<<<((3 * DD * DD / 4) + 255) / 256, 256>>>(Wqkv, 3 * DD * DD / 4, 1);
    split_hl<<<((DD * DD / 4)     + 255) / 256, 256>>>(Wo,   DD * DD / 4,     2);
    // 1) QKV projection (mma.sync bf16x3, cp.async + ldmatrix), scatter QKV
    gemm_mma<<<dim3(3 * DD / 128, MR / 128), 256, GEMM_SMEM>>>(nullptr, 3 * DD, DD, 1);
    // 2) fused causal attention -> hi/lo bf16 g_ahi/g_alo
    attn_fused<<<dim3(BB * HH, SS / 64), 256, ATT_SMEM_BYTES>>>();
    // 3) output projection (mma.sync bf16x3) -> d_out
    gemm_mma<<<dim3(DD / 128, MR / 128), 256, GEMM_SMEM>>>(out, DD, DD, 0);
}